// round 14
// baseline (speedup 1.0000x reference)
#include <cuda_runtime.h>
#include <cuda_bf16.h>
#include <cstdint>
#include <math.h>

#define Hh 128
#define Ww 128
#define HW (Hh*Ww)
#define Cc 64
#define Oo 64
#define CK 576
#define PIX 32
#define NBLK (8*HW/PIX)   // 4096

// A planes (bf16): [32 px][580 elems] per plane (1160 B rows), hi then lo
#define AROWB   1160u
#define APLANE  (PIX*1160)               // 37120 B per plane
#define SMEM_B  (2*APLANE)               // 74240 B

extern __shared__ __align__(16) char _smem_raw[];

// scratch
__device__ float g_offmask[8*27*HW];                  // [B][27][H][W]
__device__ __align__(16) float g_xt[8*HW*Cc];         // [B][H][W][C] transposed x
// DCN W fragments: [tile(8)][kk(36)][plane(2)][lane(32)] x uint2
__device__ __align__(16) uint2 g_wfrag[8*36*2*32];
// OffMask W fragments: [tile(4)][kk(36)][plane(2)][lane(32)] x uint2
__device__ __align__(16) uint2 g_wfrag_om[4*36*2*32];

// ---------------------------------------------------------------------------
// prep_w: pack weights into mma.sync B-fragment order, bf16 hi/lo planes.
// ---------------------------------------------------------------------------
__device__ __forceinline__ float wdcn_at(const float* w_dcn, int o, int k) {
    int c = k & 63, tap = k >> 6;
    return w_dcn[o*CK + c*9 + tap];
}
__device__ __forceinline__ float wom_at(const float* w_off, const float* w_mask, int o, int k) {
    int c = k & 63, tap = k >> 6;
    if (o < 18) return w_off[o*CK + c*9 + tap];
    if (o < 27) return w_mask[(o-18)*CK + c*9 + tap];
    return 0.f;
}
__device__ __forceinline__ uint2 pack4(float w0, float w1, float w2, float w3, int plane) {
    __nv_bfloat16 v0, v1, v2, v3;
    if (plane == 0) {
        v0 = __float2bfloat16(w0); v1 = __float2bfloat16(w1);
        v2 = __float2bfloat16(w2); v3 = __float2bfloat16(w3);
    } else {
        v0 = __float2bfloat16(w0 - __bfloat162float(__float2bfloat16(w0)));
        v1 = __float2bfloat16(w1 - __bfloat162float(__float2bfloat16(w1)));
        v2 = __float2bfloat16(w2 - __bfloat162float(__float2bfloat16(w2)));
        v3 = __float2bfloat16(w3 - __bfloat162float(__float2bfloat16(w3)));
    }
    __nv_bfloat162 p0; p0.x = v0; p0.y = v1;
    __nv_bfloat162 p1; p1.x = v2; p1.y = v3;
    uint2 r;
    r.x = *(uint32_t*)&p0;
    r.y = *(uint32_t*)&p1;
    return r;
}

#define NFRAG_DCN (8*36*2*32)
#define NFRAG_OM  (4*36*2*32)

__global__ void prep_w(const float* __restrict__ w_dcn,
                       const float* __restrict__ w_off,
                       const float* __restrict__ w_mask) {
    int i = blockIdx.x*256 + threadIdx.x;
    if (i < NFRAG_DCN) {
        int lane  = i & 31;
        int plane = (i >> 5) & 1;
        int kt    = i >> 6;
        int kk    = kt % 36;
        int tile  = kt / 36;
        int g  = lane >> 2;
        int t4 = lane & 3;
        int o  = tile*8 + g;
        int k0 = kk*16 + t4*2;
        g_wfrag[i] = pack4(wdcn_at(w_dcn, o, k0),   wdcn_at(w_dcn, o, k0+1),
                           wdcn_at(w_dcn, o, k0+8), wdcn_at(w_dcn, o, k0+9), plane);
    } else if (i < NFRAG_DCN + NFRAG_OM) {
        int j = i - NFRAG_DCN;
        int lane  = j & 31;
        int plane = (j >> 5) & 1;
        int kt    = j >> 6;
        int kk    = kt % 36;
        int tile  = kt / 36;
        int g  = lane >> 2;
        int t4 = lane & 3;
        int o  = tile*8 + g;
        int k0 = kk*16 + t4*2;
        g_wfrag_om[j] = pack4(wom_at(w_off, w_mask, o, k0),   wom_at(w_off, w_mask, o, k0+1),
                              wom_at(w_off, w_mask, o, k0+8), wom_at(w_off, w_mask, o, k0+9), plane);
    }
}

// ---------------------------------------------------------------------------
// prep_xt: transpose x [B][C][HW] -> g_xt [B][HW][C]. Block: 64c x 32hw tile.
// ---------------------------------------------------------------------------
__global__ __launch_bounds__(256) void prep_xt(const float* __restrict__ x) {
    __shared__ float s[32*65];
    int blk = blockIdx.x;              // 8 * 512
    int b    = blk >> 9;
    int hw0  = (blk & 511) << 5;
    int tid  = threadIdx.x;

    const float* xb = x + (size_t)b*Cc*HW;
    #pragma unroll
    for (int it = 0; it < 8; it++) {
        int i = tid + it*256;
        int c = i >> 5;
        int w = i & 31;
        s[w*65 + c] = xb[c*HW + hw0 + w];
    }
    __syncthreads();
    float* xt = g_xt + ((size_t)b*HW + hw0)*Cc;
    #pragma unroll
    for (int it = 0; it < 8; it++) {
        int i = tid + it*256;
        int w = i >> 6;
        int c = i & 63;
        xt[w*Cc + c] = s[w*65 + c];
    }
}

#define MMA(dd, a0_,a1_,a2_,a3_, b_) \
    asm volatile("mma.sync.aligned.m16n8k16.row.col.f32.bf16.bf16.f32 " \
        "{%0,%1,%2,%3}, {%4,%5,%6,%7}, {%8,%9}, {%0,%1,%2,%3};" \
        : "+f"(dd[0]), "+f"(dd[1]), "+f"(dd[2]), "+f"(dd[3]) \
        : "r"(a0_), "r"(a1_), "r"(a2_), "r"(a3_), "r"(b_.x), "r"(b_.y))

// convert float pair -> hi/lo bf16x2 words
__device__ __forceinline__ void cvt2(float v0, float v1, uint32_t& h, uint32_t& l) {
    __nv_bfloat16 h0 = __float2bfloat16(v0);
    __nv_bfloat16 h1 = __float2bfloat16(v1);
    __nv_bfloat16 l0 = __float2bfloat16(v0 - __bfloat162float(h0));
    __nv_bfloat16 l1 = __float2bfloat16(v1 - __bfloat162float(h1));
    __nv_bfloat162 hh; hh.x = h0; hh.y = h1;
    __nv_bfloat162 ll; ll.x = l0; ll.y = l1;
    h = *(uint32_t*)&hh;
    l = *(uint32_t*)&ll;
}

// ---------------------------------------------------------------------------
// Kernel A: offset/mask conv via mma.sync (reads g_xt, vectorized im2col).
// ---------------------------------------------------------------------------
__global__ __launch_bounds__(256) void offmask_kernel(
    const float* __restrict__ b_off, const float* __restrict__ b_mask)
{
    char* smA_h = _smem_raw;
    char* smA_l = _smem_raw + APLANE;

    int blk = blockIdx.x;
    int b   = blk >> 9;
    int rem = blk & 511;
    int y   = rem >> 2;
    int x0  = (rem & 3) << 5;
    int tid = threadIdx.x;

    // im2col: 288 (p,tap) tasks, 64 contiguous channels each
    for (int task = tid; task < PIX*9; task += 256) {
        int p   = task & 31;
        int tap = task >> 5;
        int ki = tap / 3;
        int kj = tap - ki*3;
        int yy = y - 1 + ki;
        int xx = x0 + p - 1 + kj;
        uint32_t rowoff = (uint32_t)p*AROWB + (uint32_t)tap*128u;
        if (yy >= 0 && yy < Hh && xx >= 0 && xx < Ww) {
            const float4* base = (const float4*)(g_xt + ((size_t)b*HW + yy*Ww + xx)*Cc);
            #pragma unroll 4
            for (int q = 0; q < 16; q++) {
                float4 v = base[q];
                uint2 hh, ll;
                cvt2(v.x, v.y, hh.x, ll.x);
                cvt2(v.z, v.w, hh.y, ll.y);
                *(uint2*)(smA_h + rowoff + q*8) = hh;
                *(uint2*)(smA_l + rowoff + q*8) = ll;
            }
        } else {
            uint2 z; z.x = 0u; z.y = 0u;
            #pragma unroll 4
            for (int q = 0; q < 16; q++) {
                *(uint2*)(smA_h + rowoff + q*8) = z;
                *(uint2*)(smA_l + rowoff + q*8) = z;
            }
        }
    }
    __syncthreads();

    int wid  = tid >> 5;
    int lane = tid & 31;
    // 8 warps: warp -> (m16 half, n8 tile): tiles 0..3 n8, mrow 0/16
    int mrow = (wid & 1) * 16;
    int tile = wid >> 1;
    int g  = lane >> 2;
    int t4 = lane & 3;

    float d[4] = {0.f,0.f,0.f,0.f};
    const uint2* fr = g_wfrag_om + (tile*36)*2*32 + lane;

    uint32_t arow0 = (uint32_t)(mrow + g)*AROWB + (uint32_t)t4*4u;
    uint32_t arow1 = arow0 + 8u*AROWB;

    #pragma unroll 4
    for (int kk = 0; kk < 36; kk++) {
        uint32_t koff = (uint32_t)kk*32u;
        uint32_t ah0 = *(const uint32_t*)(smA_h + arow0 + koff);
        uint32_t ah1 = *(const uint32_t*)(smA_h + arow1 + koff);
        uint32_t ah2 = *(const uint32_t*)(smA_h + arow0 + koff + 16u);
        uint32_t ah3 = *(const uint32_t*)(smA_h + arow1 + koff + 16u);
        uint32_t al0 = *(const uint32_t*)(smA_l + arow0 + koff);
        uint32_t al1 = *(const uint32_t*)(smA_l + arow1 + koff);
        uint32_t al2 = *(const uint32_t*)(smA_l + arow0 + koff + 16u);
        uint32_t al3 = *(const uint32_t*)(smA_l + arow1 + koff + 16u);

        uint2 bh = fr[(kk*2    )*32];
        uint2 bl = fr[(kk*2 + 1)*32];

        MMA(d, ah0,ah1,ah2,ah3, bh);
        MMA(d, ah0,ah1,ah2,ah3, bl);
        MMA(d, al0,al1,al2,al3, bh);
    }

    int px0 = x0 + mrow + g;
    int gbase = b*27*HW + y*Ww;
    #pragma unroll
    for (int e = 0; e < 2; e++) {
        int o = tile*8 + t4*2 + e;
        if (o < 27) {
            float bias = (o < 18) ? b_off[o] : b_mask[o-18];
            float r0 = d[e]   + bias;
            float r1 = d[e+2] + bias;
            if (o >= 18) {
                r0 = 1.f/(1.f+expf(-r0));
                r1 = 1.f/(1.f+expf(-r1));
            }
            g_offmask[gbase + o*HW + px0    ] = r0;
            g_offmask[gbase + o*HW + px0 + 8] = r1;
        }
    }
}

// ---------------------------------------------------------------------------
// Kernel B: deformable sampling (vectorized via g_xt) + mma.sync GEMM.
// ---------------------------------------------------------------------------
__global__ __launch_bounds__(256) void dcn_kernel(
    const float* __restrict__ b_dcn,
    float* __restrict__ out)
{
    char* smA_h = _smem_raw;
    char* smA_l = _smem_raw + APLANE;

    int blk = blockIdx.x;
    int b   = blk >> 9;
    int rem = blk & 511;
    int y   = rem >> 2;
    int x0  = (rem & 3) << 5;
    int tid = threadIdx.x;

    const float* xtb = g_xt + (size_t)b*HW*Cc;

    for (int task = tid; task < PIX*9; task += 256) {
        int p = task & 31;
        int k = task >> 5;
        int xx = x0 + p;

        const float* gb = g_offmask + b*27*HW + y*Ww + xx;
        float dy = gb[(2*k    )*HW];
        float dx = gb[(2*k + 1)*HW];
        float m  = gb[(18 + k )*HW];

        int ki = k / 3;
        int kj = k - ki*3;
        float py = (float)(y  - 1 + ki) + dy;
        float px = (float)(xx - 1 + kj) + dx;

        float fy = floorf(py), fx = floorf(px);
        float wy1 = py - fy, wx1 = px - fx;
        float wy0 = 1.f - wy1, wx0 = 1.f - wx1;

        float vy0 = (fy      >= 0.f && fy      <= 127.f) ? 1.f : 0.f;
        float vy1 = (fy+1.f  >= 0.f && fy+1.f  <= 127.f) ? 1.f : 0.f;
        float vx0 = (fx      >= 0.f && fx      <= 127.f) ? 1.f : 0.f;
        float vx1 = (fx+1.f  >= 0.f && fx+1.f  <= 127.f) ? 1.f : 0.f;

        int y0  = (int)fminf(fmaxf(fy,      0.f), 127.f);
        int y1  = (int)fminf(fmaxf(fy+1.f,  0.f), 127.f);
        int xq0 = (int)fminf(fmaxf(fx,      0.f), 127.f);
        int xq1 = (int)fminf(fmaxf(fx+1.f,  0.f), 127.f);

        float w00 = wy0*wx0*vy0*vx0*m;
        float w01 = wy0*wx1*vy0*vx1*m;
        float w10 = wy1*wx0*vy1*vx0*m;
        float w11 = wy1*wx1*vy1*vx1*m;

        const float4* p00 = (const float4*)(xtb + (size_t)(y0*Ww + xq0)*Cc);
        const float4* p01 = (const float4*)(xtb + (size_t)(y0*Ww + xq1)*Cc);
        const float4* p10 = (const float4*)(xtb + (size_t)(y1*Ww + xq0)*Cc);
        const float4* p11 = (const float4*)(xtb + (size_t)(y1*Ww + xq1)*Cc);

        uint32_t rowoff = (uint32_t)p*AROWB + (uint32_t)k*128u;
        #pragma unroll 4
        for (int q = 0; q < 16; q++) {
            float4 a0 = p00[q];
            float4 a1 = p01[q];
            float4 a2 = p10[q];
            float4 a3 = p11[q];
            float v0 = w00*a0.x + w01*a1.x + w10*a2.x + w11*a3.x;
            float v1 = w00*a0.y + w01*a1.y + w10*a2.y + w11*a3.y;
            float v2 = w00*a0.z + w01*a1.z + w10*a2.z + w11*a3.z;
            float v3 = w00*a0.w + w01*a1.w + w10*a2.w + w11*a3.w;
            uint2 hh, ll;
            cvt2(v0, v1, hh.x, ll.x);
            cvt2(v2, v3, hh.y, ll.y);
            *(uint2*)(smA_h + rowoff + q*8) = hh;
            *(uint2*)(smA_l + rowoff + q*8) = ll;
        }
    }
    __syncthreads();

    int wid  = tid >> 5;
    int lane = tid & 31;
    int mrow = (wid & 1) * 16;
    int ng   = wid >> 1;
    int g  = lane >> 2;
    int t4 = lane & 3;

    float d0[4] = {0.f,0.f,0.f,0.f};
    float d1[4] = {0.f,0.f,0.f,0.f};

    const uint2* fr0 = g_wfrag + ((ng*2    )*36)*2*32 + lane;
    const uint2* fr1 = g_wfrag + ((ng*2 + 1)*36)*2*32 + lane;

    uint32_t arow0 = (uint32_t)(mrow + g)*AROWB + (uint32_t)t4*4u;
    uint32_t arow1 = arow0 + 8u*AROWB;

    #pragma unroll 4
    for (int kk = 0; kk < 36; kk++) {
        uint32_t koff = (uint32_t)kk*32u;
        uint32_t ah0 = *(const uint32_t*)(smA_h + arow0 + koff);
        uint32_t ah1 = *(const uint32_t*)(smA_h + arow1 + koff);
        uint32_t ah2 = *(const uint32_t*)(smA_h + arow0 + koff + 16u);
        uint32_t ah3 = *(const uint32_t*)(smA_h + arow1 + koff + 16u);
        uint32_t al0 = *(const uint32_t*)(smA_l + arow0 + koff);
        uint32_t al1 = *(const uint32_t*)(smA_l + arow1 + koff);
        uint32_t al2 = *(const uint32_t*)(smA_l + arow0 + koff + 16u);
        uint32_t al3 = *(const uint32_t*)(smA_l + arow1 + koff + 16u);

        uint2 bh0 = fr0[(kk*2    )*32];
        uint2 bl0 = fr0[(kk*2 + 1)*32];
        uint2 bh1 = fr1[(kk*2    )*32];
        uint2 bl1 = fr1[(kk*2 + 1)*32];

        MMA(d0, ah0,ah1,ah2,ah3, bh0);
        MMA(d0, ah0,ah1,ah2,ah3, bl0);
        MMA(d0, al0,al1,al2,al3, bh0);
        MMA(d1, ah0,ah1,ah2,ah3, bh1);
        MMA(d1, ah0,ah1,ah2,ah3, bl1);
        MMA(d1, al0,al1,al2,al3, bh1);
    }

    int px0 = x0 + mrow + g;
    int obase = b*Oo*HW + y*Ww;
    #pragma unroll
    for (int j = 0; j < 2; j++) {
        float* dd = j ? d1 : d0;
        int on = ng*16 + j*8 + t4*2;
        float bia0 = b_dcn[on];
        float bia1 = b_dcn[on+1];
        out[obase + on*HW     + px0    ] = dd[0] + bia0;
        out[obase + (on+1)*HW + px0    ] = dd[1] + bia1;
        out[obase + on*HW     + px0 + 8] = dd[2] + bia0;
        out[obase + (on+1)*HW + px0 + 8] = dd[3] + bia1;
    }
}

extern "C" void kernel_launch(void* const* d_in, const int* in_sizes, int n_in,
                              void* d_out, int out_size)
{
    const float* x      = (const float*)d_in[0];
    const float* w_off  = (const float*)d_in[1];
    const float* b_off  = (const float*)d_in[2];
    const float* w_mask = (const float*)d_in[3];
    const float* b_mask = (const float*)d_in[4];
    const float* w_dcn  = (const float*)d_in[5];
    const float* b_dcn  = (const float*)d_in[6];
    float* out = (float*)d_out;

    cudaFuncSetAttribute(offmask_kernel, cudaFuncAttributeMaxDynamicSharedMemorySize, SMEM_B);
    cudaFuncSetAttribute(dcn_kernel,     cudaFuncAttributeMaxDynamicSharedMemorySize, SMEM_B);

    prep_w<<<108, 256>>>(w_dcn, w_off, w_mask);
    prep_xt<<<4096, 256>>>(x);
    offmask_kernel<<<NBLK, 256, SMEM_B>>>(b_off, b_mask);
    dcn_kernel<<<NBLK, 256, SMEM_B>>>(b_dcn, out);
}

// round 15
// speedup vs baseline: 1.5241x; 1.5241x over previous
#include <cuda_runtime.h>
#include <cuda_bf16.h>
#include <cstdint>
#include <math.h>

#define Hh 128
#define Ww 128
#define HW (Hh*Ww)
#define Cc 64
#define Oo 64
#define CK 576
#define PIX 32
#define NBLK (8*HW/PIX)   // 4096

// A planes (bf16): [32 px][580 elems] per plane (1160 B rows), hi then lo
#define AROWB   1160u
#define APLANE  (PIX*1160)               // 37120 B per plane
#define SMEM_B  (2*APLANE)               // 74240 B

extern __shared__ __align__(16) char _smem_raw[];

// scratch
__device__ float g_offmask[8*27*HW];                 // [B][27][H][W]
// DCN W fragments: [tile(8)][kk(36)][plane(2)][lane(32)] x uint2
__device__ __align__(16) uint2 g_wfrag[8*36*2*32];
// OffMask W fragments: [tile(4)][kk(36)][plane(2)][lane(32)] x uint2
__device__ __align__(16) uint2 g_wfrag_om[4*36*2*32];

// ---------------------------------------------------------------------------
// prep_w: pack weights into mma.sync B-fragment order, bf16 hi/lo planes.
// K ordered as k = tap*64 + c.
// ---------------------------------------------------------------------------
__device__ __forceinline__ float wdcn_at(const float* w_dcn, int o, int k) {
    int c = k & 63, tap = k >> 6;
    return w_dcn[o*CK + c*9 + tap];
}
__device__ __forceinline__ float wom_at(const float* w_off, const float* w_mask, int o, int k) {
    int c = k & 63, tap = k >> 6;
    if (o < 18) return w_off[o*CK + c*9 + tap];
    if (o < 27) return w_mask[(o-18)*CK + c*9 + tap];
    return 0.f;
}
__device__ __forceinline__ uint2 pack4(float w0, float w1, float w2, float w3, int plane) {
    __nv_bfloat16 v0, v1, v2, v3;
    if (plane == 0) {
        v0 = __float2bfloat16(w0); v1 = __float2bfloat16(w1);
        v2 = __float2bfloat16(w2); v3 = __float2bfloat16(w3);
    } else {
        v0 = __float2bfloat16(w0 - __bfloat162float(__float2bfloat16(w0)));
        v1 = __float2bfloat16(w1 - __bfloat162float(__float2bfloat16(w1)));
        v2 = __float2bfloat16(w2 - __bfloat162float(__float2bfloat16(w2)));
        v3 = __float2bfloat16(w3 - __bfloat162float(__float2bfloat16(w3)));
    }
    __nv_bfloat162 p0; p0.x = v0; p0.y = v1;
    __nv_bfloat162 p1; p1.x = v2; p1.y = v3;
    uint2 r;
    r.x = *(uint32_t*)&p0;
    r.y = *(uint32_t*)&p1;
    return r;
}

#define NFRAG_DCN (8*36*2*32)
#define NFRAG_OM  (4*36*2*32)

__global__ void prep_w(const float* __restrict__ w_dcn,
                       const float* __restrict__ w_off,
                       const float* __restrict__ w_mask) {
    int i = blockIdx.x*256 + threadIdx.x;
    if (i < NFRAG_DCN) {
        int lane  = i & 31;
        int plane = (i >> 5) & 1;
        int kt    = i >> 6;
        int kk    = kt % 36;
        int tile  = kt / 36;
        int g  = lane >> 2;
        int t4 = lane & 3;
        int o  = tile*8 + g;
        int k0 = kk*16 + t4*2;
        g_wfrag[i] = pack4(wdcn_at(w_dcn, o, k0),   wdcn_at(w_dcn, o, k0+1),
                           wdcn_at(w_dcn, o, k0+8), wdcn_at(w_dcn, o, k0+9), plane);
    } else if (i < NFRAG_DCN + NFRAG_OM) {
        int j = i - NFRAG_DCN;
        int lane  = j & 31;
        int plane = (j >> 5) & 1;
        int kt    = j >> 6;
        int kk    = kt % 36;
        int tile  = kt / 36;
        int g  = lane >> 2;
        int t4 = lane & 3;
        int o  = tile*8 + g;
        int k0 = kk*16 + t4*2;
        g_wfrag_om[j] = pack4(wom_at(w_off, w_mask, o, k0),   wom_at(w_off, w_mask, o, k0+1),
                              wom_at(w_off, w_mask, o, k0+8), wom_at(w_off, w_mask, o, k0+9), plane);
    }
}

#define MMA(dd, a0_,a1_,a2_,a3_, b_) \
    asm volatile("mma.sync.aligned.m16n8k16.row.col.f32.bf16.bf16.f32 " \
        "{%0,%1,%2,%3}, {%4,%5,%6,%7}, {%8,%9}, {%0,%1,%2,%3};" \
        : "+f"(dd[0]), "+f"(dd[1]), "+f"(dd[2]), "+f"(dd[3]) \
        : "r"(a0_), "r"(a1_), "r"(a2_), "r"(a3_), "r"(b_.x), "r"(b_.y))

// convert float pair -> hi/lo bf16x2 words
__device__ __forceinline__ void cvt2(float v0, float v1, uint32_t& h, uint32_t& l) {
    __nv_bfloat16 h0 = __float2bfloat16(v0);
    __nv_bfloat16 h1 = __float2bfloat16(v1);
    __nv_bfloat16 l0 = __float2bfloat16(v0 - __bfloat162float(h0));
    __nv_bfloat16 l1 = __float2bfloat16(v1 - __bfloat162float(h1));
    __nv_bfloat162 hh; hh.x = h0; hh.y = h1;
    __nv_bfloat162 ll; ll.x = l0; ll.y = l1;
    h = *(uint32_t*)&hh;
    l = *(uint32_t*)&ll;
}

// ---------------------------------------------------------------------------
// Kernel A: offset/mask conv via mma.sync.
// Dedup im2col: 102 distinct source points x 2 channel halves = 204 tasks.
// Each point is loaded+converted ONCE and scattered to its <=3 tap slots.
// ---------------------------------------------------------------------------
__global__ __launch_bounds__(256) void offmask_kernel(
    const float* __restrict__ x,
    const float* __restrict__ b_off, const float* __restrict__ b_mask)
{
    char* smA_h = _smem_raw;
    char* smA_l = _smem_raw + APLANE;

    int blk = blockIdx.x;
    int b   = blk >> 9;
    int rem = blk & 511;
    int y   = rem >> 2;
    int x0  = (rem & 3) << 5;
    int tid = threadIdx.x;

    const float* xb = x + b*Cc*HW;

    // 204 tasks: t = point*2 + half; point = r*34 + cx (r 0..2, cx 0..33)
    if (tid < 204) {
        int point = tid >> 1;
        int half  = tid & 1;
        int r  = point / 34;
        int cx = point - r*34;
        int yy = y - 1 + r;
        int xx = x0 - 1 + cx;
        int c0 = half << 5;                 // 32 channels

        // target (p, tap) slots: p = cx - kj, tap = r*3 + kj
        uint32_t dsts[3]; int nd = 0;
        #pragma unroll
        for (int kj = 0; kj < 3; kj++) {
            int p = cx - kj;
            if (p >= 0 && p < 32)
                dsts[nd++] = (uint32_t)p*AROWB + (uint32_t)(r*3+kj)*128u + (uint32_t)c0*2u;
        }

        bool inb = (yy >= 0 && yy < Hh && xx >= 0 && xx < Ww);
        const float* base = xb + c0*HW + (inb ? (yy*Ww + xx) : 0);

        #pragma unroll 8
        for (int c = 0; c < 32; c += 2) {
            float v0 = inb ? base[c*HW]     : 0.f;
            float v1 = inb ? base[(c+1)*HW] : 0.f;
            uint32_t hh, ll;
            cvt2(v0, v1, hh, ll);
            #pragma unroll
            for (int dsel = 0; dsel < 3; dsel++) {
                if (dsel < nd) {
                    *(uint32_t*)(smA_h + dsts[dsel] + c*2) = hh;
                    *(uint32_t*)(smA_l + dsts[dsel] + c*2) = ll;
                }
            }
        }
    }
    __syncthreads();

    int wid  = tid >> 5;
    int lane = tid & 31;
    int mrow = (wid & 1) * 16;
    int tile = wid >> 1;
    int g  = lane >> 2;
    int t4 = lane & 3;

    float d[4] = {0.f,0.f,0.f,0.f};
    const uint2* fr = g_wfrag_om + (tile*36)*2*32 + lane;

    uint32_t arow0 = (uint32_t)(mrow + g)*AROWB + (uint32_t)t4*4u;
    uint32_t arow1 = arow0 + 8u*AROWB;

    #pragma unroll 4
    for (int kk = 0; kk < 36; kk++) {
        uint32_t koff = (uint32_t)kk*32u;
        uint32_t ah0 = *(const uint32_t*)(smA_h + arow0 + koff);
        uint32_t ah1 = *(const uint32_t*)(smA_h + arow1 + koff);
        uint32_t ah2 = *(const uint32_t*)(smA_h + arow0 + koff + 16u);
        uint32_t ah3 = *(const uint32_t*)(smA_h + arow1 + koff + 16u);
        uint32_t al0 = *(const uint32_t*)(smA_l + arow0 + koff);
        uint32_t al1 = *(const uint32_t*)(smA_l + arow1 + koff);
        uint32_t al2 = *(const uint32_t*)(smA_l + arow0 + koff + 16u);
        uint32_t al3 = *(const uint32_t*)(smA_l + arow1 + koff + 16u);

        uint2 bh = fr[(kk*2    )*32];
        uint2 bl = fr[(kk*2 + 1)*32];

        MMA(d, ah0,ah1,ah2,ah3, bh);
        MMA(d, ah0,ah1,ah2,ah3, bl);
        MMA(d, al0,al1,al2,al3, bh);
    }

    int px0 = x0 + mrow + g;
    int gbase = b*27*HW + y*Ww;
    #pragma unroll
    for (int e = 0; e < 2; e++) {
        int o = tile*8 + t4*2 + e;
        if (o < 27) {
            float bias = (o < 18) ? b_off[o] : b_mask[o-18];
            float r0 = d[e]   + bias;
            float r1 = d[e+2] + bias;
            if (o >= 18) {
                r0 = 1.f/(1.f+expf(-r0));
                r1 = 1.f/(1.f+expf(-r1));
            }
            g_offmask[gbase + o*HW + px0    ] = r0;
            g_offmask[gbase + o*HW + px0 + 8] = r1;
        }
    }
}

// ---------------------------------------------------------------------------
// Kernel B: deformable sampling (NCHW, 576 half-tasks) + mma.sync GEMM.
// ---------------------------------------------------------------------------
__global__ __launch_bounds__(256) void dcn_kernel(
    const float* __restrict__ x,
    const float* __restrict__ b_dcn,
    float* __restrict__ out)
{
    char* smA_h = _smem_raw;
    char* smA_l = _smem_raw + APLANE;

    int blk = blockIdx.x;
    int b   = blk >> 9;
    int rem = blk & 511;
    int y   = rem >> 2;
    int x0  = (rem & 3) << 5;
    int tid = threadIdx.x;

    const float* xb = x + b*Cc*HW;

    // 576 half-tasks: p = t&31, kh = t>>5 (0..17): k = kh>>1, half = kh&1
    for (int t = tid; t < PIX*9*2; t += 256) {
        int p  = t & 31;
        int kh = t >> 5;
        int k    = kh >> 1;
        int half = kh & 1;
        int xx = x0 + p;

        const float* gb = g_offmask + b*27*HW + y*Ww + xx;
        float dy = gb[(2*k    )*HW];
        float dx = gb[(2*k + 1)*HW];
        float m  = gb[(18 + k )*HW];

        int ki = k / 3;
        int kj = k - ki*3;
        float py = (float)(y  - 1 + ki) + dy;
        float px = (float)(xx - 1 + kj) + dx;

        float fy = floorf(py), fx = floorf(px);
        float wy1 = py - fy, wx1 = px - fx;
        float wy0 = 1.f - wy1, wx0 = 1.f - wx1;

        float vy0 = (fy      >= 0.f && fy      <= 127.f) ? 1.f : 0.f;
        float vy1 = (fy+1.f  >= 0.f && fy+1.f  <= 127.f) ? 1.f : 0.f;
        float vx0 = (fx      >= 0.f && fx      <= 127.f) ? 1.f : 0.f;
        float vx1 = (fx+1.f  >= 0.f && fx+1.f  <= 127.f) ? 1.f : 0.f;

        int y0  = (int)fminf(fmaxf(fy,      0.f), 127.f);
        int y1  = (int)fminf(fmaxf(fy+1.f,  0.f), 127.f);
        int xq0 = (int)fminf(fmaxf(fx,      0.f), 127.f);
        int xq1 = (int)fminf(fmaxf(fx+1.f,  0.f), 127.f);

        int o00 = y0*Ww + xq0, o01 = y0*Ww + xq1;
        int o10 = y1*Ww + xq0, o11 = y1*Ww + xq1;
        float w00 = wy0*wx0*vy0*vx0*m;
        float w01 = wy0*wx1*vy0*vx1*m;
        float w10 = wy1*wx0*vy1*vx0*m;
        float w11 = wy1*wx1*vy1*vx1*m;

        int c0 = half << 5;
        uint32_t rowoff = (uint32_t)p*AROWB + (uint32_t)k*128u + (uint32_t)c0*2u;
        const float* xc = xb + c0*HW;
        #pragma unroll 8
        for (int c = 0; c < 32; c += 2) {
            const float* cp0 = xc;
            const float* cp1 = xc + HW;
            float v0 = w00*cp0[o00] + w01*cp0[o01] + w10*cp0[o10] + w11*cp0[o11];
            float v1 = w00*cp1[o00] + w01*cp1[o01] + w10*cp1[o10] + w11*cp1[o11];
            uint32_t hh, ll;
            cvt2(v0, v1, hh, ll);
            *(uint32_t*)(smA_h + rowoff + c*2) = hh;
            *(uint32_t*)(smA_l + rowoff + c*2) = ll;
            xc += 2*HW;
        }
    }
    __syncthreads();

    int wid  = tid >> 5;
    int lane = tid & 31;
    int mrow = (wid & 1) * 16;
    int ng   = wid >> 1;
    int g  = lane >> 2;
    int t4 = lane & 3;

    float d0[4] = {0.f,0.f,0.f,0.f};
    float d1[4] = {0.f,0.f,0.f,0.f};

    const uint2* fr0 = g_wfrag + ((ng*2    )*36)*2*32 + lane;
    const uint2* fr1 = g_wfrag + ((ng*2 + 1)*36)*2*32 + lane;

    uint32_t arow0 = (uint32_t)(mrow + g)*AROWB + (uint32_t)t4*4u;
    uint32_t arow1 = arow0 + 8u*AROWB;

    #pragma unroll 4
    for (int kk = 0; kk < 36; kk++) {
        uint32_t koff = (uint32_t)kk*32u;
        uint32_t ah0 = *(const uint32_t*)(smA_h + arow0 + koff);
        uint32_t ah1 = *(const uint32_t*)(smA_h + arow1 + koff);
        uint32_t ah2 = *(const uint32_t*)(smA_h + arow0 + koff + 16u);
        uint32_t ah3 = *(const uint32_t*)(smA_h + arow1 + koff + 16u);
        uint32_t al0 = *(const uint32_t*)(smA_l + arow0 + koff);
        uint32_t al1 = *(const uint32_t*)(smA_l + arow1 + koff);
        uint32_t al2 = *(const uint32_t*)(smA_l + arow0 + koff + 16u);
        uint32_t al3 = *(const uint32_t*)(smA_l + arow1 + koff + 16u);

        uint2 bh0 = fr0[(kk*2    )*32];
        uint2 bl0 = fr0[(kk*2 + 1)*32];
        uint2 bh1 = fr1[(kk*2    )*32];
        uint2 bl1 = fr1[(kk*2 + 1)*32];

        MMA(d0, ah0,ah1,ah2,ah3, bh0);
        MMA(d0, ah0,ah1,ah2,ah3, bl0);
        MMA(d0, al0,al1,al2,al3, bh0);
        MMA(d1, ah0,ah1,ah2,ah3, bh1);
        MMA(d1, ah0,ah1,ah2,ah3, bl1);
        MMA(d1, al0,al1,al2,al3, bh1);
    }

    int px0 = x0 + mrow + g;
    int obase = b*Oo*HW + y*Ww;
    #pragma unroll
    for (int j = 0; j < 2; j++) {
        float* dd = j ? d1 : d0;
        int on = ng*16 + j*8 + t4*2;
        float bia0 = b_dcn[on];
        float bia1 = b_dcn[on+1];
        out[obase + on*HW     + px0    ] = dd[0] + bia0;
        out[obase + (on+1)*HW + px0    ] = dd[1] + bia1;
        out[obase + on*HW     + px0 + 8] = dd[2] + bia0;
        out[obase + (on+1)*HW + px0 + 8] = dd[3] + bia1;
    }
}

extern "C" void kernel_launch(void* const* d_in, const int* in_sizes, int n_in,
                              void* d_out, int out_size)
{
    const float* x      = (const float*)d_in[0];
    const float* w_off  = (const float*)d_in[1];
    const float* b_off  = (const float*)d_in[2];
    const float* w_mask = (const float*)d_in[3];
    const float* b_mask = (const float*)d_in[4];
    const float* w_dcn  = (const float*)d_in[5];
    const float* b_dcn  = (const float*)d_in[6];
    float* out = (float*)d_out;

    cudaFuncSetAttribute(offmask_kernel, cudaFuncAttributeMaxDynamicSharedMemorySize, SMEM_B);
    cudaFuncSetAttribute(dcn_kernel,     cudaFuncAttributeMaxDynamicSharedMemorySize, SMEM_B);

    prep_w<<<108, 256>>>(w_dcn, w_off, w_mask);
    offmask_kernel<<<NBLK, 256, SMEM_B>>>(x, b_off, b_mask);
    dcn_kernel<<<NBLK, 256, SMEM_B>>>(x, b_dcn, out);
}